// round 4
// baseline (speedup 1.0000x reference)
#include <cuda_runtime.h>
#include <cuda_bf16.h>
#include <mma.h>
#include <cstdint>

using namespace nvcuda;

#define NN 50000
#define HH 128
#define OUTC 64
#define DEPTH 3
#define LN_EPS 1e-5f
#define EGMAX 600000
#define ELMAX 400000
#define NB196 196
#define TILES 391          // ceil(NN/128)
#define LDT 48             // smem tile leading dim (bf16 elems): rows 96B, 32B-aligned at k-steps

// ================= scratch =================
__device__ float g_x[NN * HH];
__device__ float g_hG[NN * HH];
__device__ float g_hL[NN * HH];
__device__ float g_xcat[NN * 2 * HH];
__device__ int   g_degG[NN];
__device__ int   g_degL[NN];
__device__ float g_dinvG[NN];
__device__ float g_dinvL[NN];
__device__ int   g_rowptrG[NN + 1];
__device__ int   g_rowptrL[NN + 1];
__device__ int   g_fillG[NN];
__device__ int   g_fillL[NN];
__device__ int   g_colG[EGMAX];
__device__ int   g_colL[ELMAX];
__device__ float g_coefG[EGMAX];
__device__ float g_coefL[ELMAX];
__device__ int   g_bsum[256];
// bf16-split transposed weights [layer][N][K]
__device__ __nv_bfloat16 g_BGh[DEPTH * HH * HH];
__device__ __nv_bfloat16 g_BGl[DEPTH * HH * HH];
__device__ __nv_bfloat16 g_BLh[DEPTH * HH * HH];
__device__ __nv_bfloat16 g_BLl[DEPTH * HH * HH];
__device__ __nv_bfloat16 g_Blinh[DEPTH * HH * 2 * HH];
__device__ __nv_bfloat16 g_Blinl[DEPTH * HH * 2 * HH];
__device__ __nv_bfloat16 g_Bfinh[OUTC * HH];
__device__ __nv_bfloat16 g_Bfinl[OUTC * HH];

// ================= degree / dinv / CSR =================
__global__ void zero_deg_kernel(int* degG, int* degL, int n) {
    int i = blockIdx.x * blockDim.x + threadIdx.x;
    if (i < n) { degG[i] = 0; degL[i] = 0; }
}
__global__ void count_deg_kernel(const int* __restrict__ dst, int E, int* __restrict__ deg) {
    int i = blockIdx.x * blockDim.x + threadIdx.x;
    if (i < E) atomicAdd(&deg[dst[i]], 1);
}
__global__ void make_dinv_kernel(const int* __restrict__ degG, float* __restrict__ dinvG,
                                 const int* __restrict__ degL, float* __restrict__ dinvL, int n) {
    int i = blockIdx.x * blockDim.x + threadIdx.x;
    if (i < n) {
        dinvG[i] = rsqrtf((float)degG[i] + 2.0f);
        dinvL[i] = rsqrtf((float)degL[i] + 2.0f);
    }
}
__global__ void scan_block_kernel(const int* __restrict__ deg, int* __restrict__ rowptr,
                                  int* __restrict__ bsum, int n) {
    __shared__ int s[256];
    int i = blockIdx.x * 256 + threadIdx.x;
    int v = (i < n) ? deg[i] : 0;
    s[threadIdx.x] = v;
    __syncthreads();
    #pragma unroll
    for (int o = 1; o < 256; o <<= 1) {
        int t = (threadIdx.x >= o) ? s[threadIdx.x - o] : 0;
        __syncthreads();
        s[threadIdx.x] += t;
        __syncthreads();
    }
    if (i < n) rowptr[i] = s[threadIdx.x] - v;
    if (threadIdx.x == 255) bsum[blockIdx.x] = s[255];
}
__global__ void scan_aux_kernel(int* bsum, int nb) {
    if (threadIdx.x == 0 && blockIdx.x == 0) {
        int run = 0;
        for (int i = 0; i < nb; i++) { int t = bsum[i]; bsum[i] = run; run += t; }
    }
}
__global__ void scan_add_kernel(int* __restrict__ rowptr, int* __restrict__ fill,
                                const int* __restrict__ bsum, int n, int E) {
    int i = blockIdx.x * 256 + threadIdx.x;
    if (i < n) {
        int v = rowptr[i] + bsum[i >> 8];
        rowptr[i] = v;
        fill[i] = v;
    }
    if (i == 0) rowptr[n] = E;
}
__global__ void fill_csr_kernel(const int* __restrict__ src, const int* __restrict__ dst, int E,
                                int* __restrict__ fill, int* __restrict__ col,
                                float* __restrict__ coef, const float* __restrict__ dinv) {
    int e = blockIdx.x * blockDim.x + threadIdx.x;
    if (e < E) {
        int s = src[e], d = dst[e];
        int p = atomicAdd(&fill[d], 1);
        col[p] = s;
        coef[p] = dinv[s] * dinv[d];
    }
}

// ================= weight transpose + bf16 split =================
// W [layer][K][N] row-major -> Bh/Bl [layer][N][K]
__global__ void wsplit_kernel(const float* __restrict__ W, __nv_bfloat16* __restrict__ Bh,
                              __nv_bfloat16* __restrict__ Bl, int K, int N) {
    __shared__ float t[32][33];
    const float* Wl = W + (size_t)blockIdx.z * K * N;
    __nv_bfloat16* Bhl = Bh + (size_t)blockIdx.z * K * N;
    __nv_bfloat16* Bll = Bl + (size_t)blockIdx.z * K * N;
    int n0 = blockIdx.x * 32, k0 = blockIdx.y * 32;
    int tx = threadIdx.x, ty = threadIdx.y;
    #pragma unroll
    for (int i = 0; i < 4; i++)
        t[ty + i * 8][tx] = Wl[(size_t)(k0 + ty + i * 8) * N + n0 + tx];
    __syncthreads();
    #pragma unroll
    for (int i = 0; i < 4; i++) {
        float v = t[tx][ty + i * 8];
        __nv_bfloat16 h = __float2bfloat16(v);
        __nv_bfloat16 l = __float2bfloat16(v - __bfloat162float(h));
        size_t o = (size_t)(n0 + ty + i * 8) * K + k0 + tx;
        Bhl[o] = h;
        Bll[o] = l;
    }
}

// ================= wmma bf16x3 GEMM =================
// C[M,N] = A[M,K] @ Bt^T + bias ;  Bt stored [N,K] row-major, pre-split hi/lo (bf16)
// CTA tile 128 x N (N = 128 or 64). 8 warps in 4x2. grid.y selects (B,C) pair.
__global__ __launch_bounds__(256)
void gemm_bf16x3_kernel(const float* __restrict__ A, int lda,
                        const __nv_bfloat16* __restrict__ Bh0, const __nv_bfloat16* __restrict__ Bl0,
                        const __nv_bfloat16* __restrict__ Bh1, const __nv_bfloat16* __restrict__ Bl1,
                        float* __restrict__ C0, float* __restrict__ C1,
                        const float* __restrict__ bias, int M, int K, int N) {
    extern __shared__ char sm[];
    __nv_bfloat16* Ahs = (__nv_bfloat16*)sm;        // [128][LDT]
    __nv_bfloat16* Als = Ahs + 128 * LDT;
    __nv_bfloat16* Bhs = Als + 128 * LDT;
    __nv_bfloat16* Bls = Bhs + 128 * LDT;
    float* stage = (float*)sm;                      // reused after main loop

    const __nv_bfloat16* gBh = blockIdx.y ? Bh1 : Bh0;
    const __nv_bfloat16* gBl = blockIdx.y ? Bl1 : Bl0;
    float* C = blockIdx.y ? C1 : C0;

    const int tid = threadIdx.x;
    const int wid = tid >> 5;
    const int lane = tid & 31;
    const int wr = wid >> 1;        // 0..3 (32 rows each)
    const int wc = wid & 1;         // 0..1
    const int row0 = blockIdx.x * 128;
    const int halfN = N >> 1;       // 64 or 32
    const int nf = halfN >> 4;      // 4 or 2

    wmma::fragment<wmma::accumulator, 16, 16, 16, float> acc[2][4];
    #pragma unroll
    for (int i = 0; i < 2; i++)
        #pragma unroll
        for (int j = 0; j < 4; j++)
            wmma::fill_fragment(acc[i][j], 0.0f);

    for (int kc = 0; kc < K; kc += 32) {
        // ---- load A 128x32 fp32 -> split bf16 hi/lo into smem ----
        #pragma unroll
        for (int it = 0; it < 4; it++) {
            int idx = tid + it * 256;       // 0..1023
            int r = idx >> 3;
            int c4 = (idx & 7) * 4;
            int gr = row0 + r;
            float4 v = make_float4(0.f, 0.f, 0.f, 0.f);
            if (gr < M) v = *reinterpret_cast<const float4*>(&A[(size_t)gr * lda + kc + c4]);
            __nv_bfloat16 hx = __float2bfloat16(v.x);
            __nv_bfloat16 hy = __float2bfloat16(v.y);
            __nv_bfloat16 hz = __float2bfloat16(v.z);
            __nv_bfloat16 hw = __float2bfloat16(v.w);
            __nv_bfloat16 lx = __float2bfloat16(v.x - __bfloat162float(hx));
            __nv_bfloat16 ly = __float2bfloat16(v.y - __bfloat162float(hy));
            __nv_bfloat16 lz = __float2bfloat16(v.z - __bfloat162float(hz));
            __nv_bfloat16 lw = __float2bfloat16(v.w - __bfloat162float(hw));
            __nv_bfloat162* ph = reinterpret_cast<__nv_bfloat162*>(&Ahs[r * LDT + c4]);
            __nv_bfloat162* pl = reinterpret_cast<__nv_bfloat162*>(&Als[r * LDT + c4]);
            ph[0] = __nv_bfloat162(hx, hy);
            ph[1] = __nv_bfloat162(hz, hw);
            pl[0] = __nv_bfloat162(lx, ly);
            pl[1] = __nv_bfloat162(lz, lw);
        }
        // ---- load B Nx32 bf16 (pre-split) into smem ----
        for (int g = tid; g < N * 4; g += 256) {
            int n = g >> 2;
            int kk = (g & 3) * 8;
            *reinterpret_cast<int4*>(&Bhs[n * LDT + kk]) =
                *reinterpret_cast<const int4*>(&gBh[(size_t)n * K + kc + kk]);
            *reinterpret_cast<int4*>(&Bls[n * LDT + kk]) =
                *reinterpret_cast<const int4*>(&gBl[(size_t)n * K + kc + kk]);
        }
        __syncthreads();

        #pragma unroll
        for (int ks = 0; ks < 32; ks += 16) {
            wmma::fragment<wmma::matrix_a, 16, 16, 16, __nv_bfloat16, wmma::row_major> fah[2], fal[2];
            #pragma unroll
            for (int i = 0; i < 2; i++) {
                wmma::load_matrix_sync(fah[i], &Ahs[(wr * 32 + i * 16) * LDT + ks], LDT);
                wmma::load_matrix_sync(fal[i], &Als[(wr * 32 + i * 16) * LDT + ks], LDT);
            }
            wmma::fragment<wmma::matrix_b, 16, 16, 16, __nv_bfloat16, wmma::col_major> fbh[4], fbl[4];
            for (int j = 0; j < nf; j++) {
                wmma::load_matrix_sync(fbh[j], &Bhs[(wc * halfN + j * 16) * LDT + ks], LDT);
                wmma::load_matrix_sync(fbl[j], &Bls[(wc * halfN + j * 16) * LDT + ks], LDT);
            }
            #pragma unroll
            for (int i = 0; i < 2; i++)
                for (int j = 0; j < nf; j++) {
                    wmma::mma_sync(acc[i][j], fah[i], fbh[j], acc[i][j]);
                    wmma::mma_sync(acc[i][j], fah[i], fbl[j], acc[i][j]);
                    wmma::mma_sync(acc[i][j], fal[i], fbh[j], acc[i][j]);
                }
        }
        __syncthreads();
    }

    // ---- epilogue through smem staging (smem reuse is safe after last sync) ----
    float* st = stage + wid * 320;      // 16x20 per warp
    #pragma unroll
    for (int i = 0; i < 2; i++)
        for (int j = 0; j < nf; j++) {
            wmma::store_matrix_sync(st, acc[i][j], 20, wmma::mem_row_major);
            __syncwarp();
            #pragma unroll
            for (int e = 0; e < 8; e++) {
                int idx = lane + e * 32;
                int r = idx >> 4;
                int c = idx & 15;
                int grow = row0 + wr * 32 + i * 16 + r;
                int gcol = wc * halfN + j * 16 + c;
                if (grow < M) {
                    float v = st[r * 20 + c];
                    if (bias) v += __ldg(&bias[gcol]);
                    C[(size_t)grow * N + gcol] = v;
                }
            }
            __syncwarp();
        }
}

// ================= fused gather + LN + ReLU + residual + concat (both branches via grid.y) ====
__global__ void gather_ln_kernel(const float4* __restrict__ hG4, const float4* __restrict__ hL4,
                                 const float4* __restrict__ x4,
                                 const int* __restrict__ rowG, const int* __restrict__ rowL,
                                 const int* __restrict__ colG, const int* __restrict__ colL,
                                 const float* __restrict__ coefG, const float* __restrict__ coefL,
                                 const float* __restrict__ dinvG, const float* __restrict__ dinvL,
                                 const float4* __restrict__ biasG4, const float4* __restrict__ biasL4,
                                 const float4* __restrict__ g4, const float4* __restrict__ b4,
                                 float4* __restrict__ xcat4, int residual) {
    int warp = (blockIdx.x * blockDim.x + threadIdx.x) >> 5;
    int lane = threadIdx.x & 31;
    if (warp >= NN) return;
    int n = warp;
    int half = blockIdx.y;

    const float4* h4 = half ? hL4 : hG4;
    const int* rowptr = half ? rowL : rowG;
    const int* col = half ? colL : colG;
    const float* coef = half ? coefL : coefG;
    const float* dinv = half ? dinvL : dinvG;
    const float4* bias4 = half ? biasL4 : biasG4;

    float dv = __ldg(&dinv[n]);
    float sl = 2.0f * dv * dv;
    float4 h = h4[n * 32 + lane];
    float4 bb = __ldg(&bias4[lane]);
    float4 acc;
    acc.x = h.x * sl + bb.x;
    acc.y = h.y * sl + bb.y;
    acc.z = h.z * sl + bb.z;
    acc.w = h.w * sl + bb.w;

    int e = __ldg(&rowptr[n]);
    int e1 = __ldg(&rowptr[n + 1]);
    for (; e + 1 < e1; e += 2) {
        int s0 = __ldg(&col[e]);
        int s1 = __ldg(&col[e + 1]);
        float c0 = __ldg(&coef[e]);
        float c1 = __ldg(&coef[e + 1]);
        float4 v0 = h4[s0 * 32 + lane];
        float4 v1 = h4[s1 * 32 + lane];
        acc.x += c0 * v0.x + c1 * v1.x;
        acc.y += c0 * v0.y + c1 * v1.y;
        acc.z += c0 * v0.z + c1 * v1.z;
        acc.w += c0 * v0.w + c1 * v1.w;
    }
    if (e < e1) {
        int s0 = __ldg(&col[e]);
        float c0 = __ldg(&coef[e]);
        float4 v0 = h4[s0 * 32 + lane];
        acc.x += c0 * v0.x; acc.y += c0 * v0.y; acc.z += c0 * v0.z; acc.w += c0 * v0.w;
    }

    float s1 = acc.x + acc.y + acc.z + acc.w;
    float s2 = acc.x * acc.x + acc.y * acc.y + acc.z * acc.z + acc.w * acc.w;
    #pragma unroll
    for (int o = 16; o > 0; o >>= 1) {
        s1 += __shfl_xor_sync(0xffffffffu, s1, o);
        s2 += __shfl_xor_sync(0xffffffffu, s2, o);
    }
    float mu = s1 * (1.0f / HH);
    float var = s2 * (1.0f / HH) - mu * mu;
    float rstd = rsqrtf(var + LN_EPS);

    float4 gg = __ldg(&g4[lane]);
    float4 be = __ldg(&b4[lane]);
    float4 y;
    y.x = fmaxf((acc.x - mu) * rstd * gg.x + be.x, 0.0f);
    y.y = fmaxf((acc.y - mu) * rstd * gg.y + be.y, 0.0f);
    y.z = fmaxf((acc.z - mu) * rstd * gg.z + be.z, 0.0f);
    y.w = fmaxf((acc.w - mu) * rstd * gg.w + be.w, 0.0f);
    if (residual) {
        float4 xv = x4[n * 32 + lane];
        y.x += xv.x; y.y += xv.y; y.z += xv.z; y.w += xv.w;
    }
    xcat4[n * 64 + half * 32 + lane] = y;
}

// ================= launch =================
extern "C" void kernel_launch(void* const* d_in, const int* in_sizes, int n_in,
                              void* d_out, int out_size) {
    const float* x_in  = (const float*)d_in[0];
    const float* WL    = (const float*)d_in[1];
    const float* bL    = (const float*)d_in[2];
    const float* WG    = (const float*)d_in[3];
    const float* bG    = (const float*)d_in[4];
    const float* linW  = (const float*)d_in[5];
    const float* linb  = (const float*)d_in[6];
    const float* ln_g  = (const float*)d_in[7];
    const float* ln_b  = (const float*)d_in[8];
    const float* finW  = (const float*)d_in[9];
    const float* finb  = (const float*)d_in[10];
    const int*   Ge    = (const int*)d_in[11];
    const int*   Le    = (const int*)d_in[12];
    int E_G = in_sizes[11] / 2;
    int E_L = in_sizes[12] / 2;
    float* out = (float*)d_out;

    float *px, *phG, *phL, *pxcat, *pdinvG, *pdinvL, *pcoefG, *pcoefL;
    int *pdegG, *pdegL, *prowG, *prowL, *pfillG, *pfillL, *pcolG, *pcolL, *pbsum;
    __nv_bfloat16 *pBGh, *pBGl, *pBLh, *pBLl, *pBlinh, *pBlinl, *pBfinh, *pBfinl;
    cudaGetSymbolAddress((void**)&px,     g_x);
    cudaGetSymbolAddress((void**)&phG,    g_hG);
    cudaGetSymbolAddress((void**)&phL,    g_hL);
    cudaGetSymbolAddress((void**)&pxcat,  g_xcat);
    cudaGetSymbolAddress((void**)&pdegG,  g_degG);
    cudaGetSymbolAddress((void**)&pdegL,  g_degL);
    cudaGetSymbolAddress((void**)&pdinvG, g_dinvG);
    cudaGetSymbolAddress((void**)&pdinvL, g_dinvL);
    cudaGetSymbolAddress((void**)&prowG,  g_rowptrG);
    cudaGetSymbolAddress((void**)&prowL,  g_rowptrL);
    cudaGetSymbolAddress((void**)&pfillG, g_fillG);
    cudaGetSymbolAddress((void**)&pfillL, g_fillL);
    cudaGetSymbolAddress((void**)&pcolG,  g_colG);
    cudaGetSymbolAddress((void**)&pcolL,  g_colL);
    cudaGetSymbolAddress((void**)&pcoefG, g_coefG);
    cudaGetSymbolAddress((void**)&pcoefL, g_coefL);
    cudaGetSymbolAddress((void**)&pbsum,  g_bsum);
    cudaGetSymbolAddress((void**)&pBGh,   g_BGh);
    cudaGetSymbolAddress((void**)&pBGl,   g_BGl);
    cudaGetSymbolAddress((void**)&pBLh,   g_BLh);
    cudaGetSymbolAddress((void**)&pBLl,   g_BLl);
    cudaGetSymbolAddress((void**)&pBlinh, g_Blinh);
    cudaGetSymbolAddress((void**)&pBlinl, g_Blinl);
    cudaGetSymbolAddress((void**)&pBfinh, g_Bfinh);
    cudaGetSymbolAddress((void**)&pBfinl, g_Bfinl);

    const int GEMM_SMEM = 4 * 128 * LDT * 2;   // 49152 bytes

    cudaMemcpyAsync(px, x_in, (size_t)NN * HH * sizeof(float), cudaMemcpyDeviceToDevice);

    // degrees + dinv + CSR
    zero_deg_kernel<<<NB196, 256>>>(pdegG, pdegL, NN);
    count_deg_kernel<<<(E_G + 255) / 256, 256>>>(Ge + E_G, E_G, pdegG);
    count_deg_kernel<<<(E_L + 255) / 256, 256>>>(Le + E_L, E_L, pdegL);
    make_dinv_kernel<<<NB196, 256>>>(pdegG, pdinvG, pdegL, pdinvL, NN);
    scan_block_kernel<<<NB196, 256>>>(pdegG, prowG, pbsum, NN);
    scan_aux_kernel<<<1, 32>>>(pbsum, NB196);
    scan_add_kernel<<<NB196, 256>>>(prowG, pfillG, pbsum, NN, E_G);
    fill_csr_kernel<<<(E_G + 255) / 256, 256>>>(Ge, Ge + E_G, E_G, pfillG, pcolG, pcoefG, pdinvG);
    scan_block_kernel<<<NB196, 256>>>(pdegL, prowL, pbsum, NN);
    scan_aux_kernel<<<1, 32>>>(pbsum, NB196);
    scan_add_kernel<<<NB196, 256>>>(prowL, pfillL, pbsum, NN, E_L);
    fill_csr_kernel<<<(E_L + 255) / 256, 256>>>(Le, Le + E_L, E_L, pfillL, pcolL, pcoefL, pdinvL);

    // weight preprocessing: transpose + bf16 split
    dim3 wb(32, 8);
    wsplit_kernel<<<dim3(4, 4, DEPTH), wb>>>(WG, pBGh, pBGl, HH, HH);
    wsplit_kernel<<<dim3(4, 4, DEPTH), wb>>>(WL, pBLh, pBLl, HH, HH);
    wsplit_kernel<<<dim3(4, 8, DEPTH), wb>>>(linW, pBlinh, pBlinl, 2 * HH, HH);
    wsplit_kernel<<<dim3(2, 4, 1),     wb>>>(finW, pBfinh, pBfinl, HH, OUTC);

    int gatherBlocks = (NN * 32 + 255) / 256;

    for (int i = 0; i < DEPTH; i++) {
        size_t wo = (size_t)i * HH * HH;
        // fused dual-branch GEMM: grid.y=0 -> G, 1 -> L
        gemm_bf16x3_kernel<<<dim3(TILES, 2), 256, GEMM_SMEM>>>(
            px, HH, pBGh + wo, pBGl + wo, pBLh + wo, pBLl + wo,
            phG, phL, nullptr, NN, HH, HH);
        int res = (i > 0) ? 1 : 0;
        gather_ln_kernel<<<dim3(gatherBlocks, 2), 256>>>(
            (const float4*)phG, (const float4*)phL, (const float4*)px,
            prowG, prowL, pcolG, pcolL, pcoefG, pcoefL, pdinvG, pdinvL,
            (const float4*)(bG + (size_t)i * HH), (const float4*)(bL + (size_t)i * HH),
            (const float4*)ln_g, (const float4*)ln_b, (float4*)pxcat, res);
        // concat linear: x = xcat @ linW + linb
        size_t lo = (size_t)i * HH * 2 * HH;
        gemm_bf16x3_kernel<<<dim3(TILES, 1), 256, GEMM_SMEM>>>(
            pxcat, 2 * HH, pBlinh + lo, pBlinl + lo, nullptr, nullptr,
            px, nullptr, linb + (size_t)i * HH, NN, 2 * HH, HH);
    }

    // final projection (N=64)
    gemm_bf16x3_kernel<<<dim3(TILES, 1), 256, GEMM_SMEM>>>(
        px, HH, pBfinh, pBfinl, nullptr, nullptr,
        out, nullptr, finb, NN, HH, OUTC);
    cudaMemcpyAsync(out + (size_t)NN * OUTC, px, (size_t)NN * HH * sizeof(float),
                    cudaMemcpyDeviceToDevice);
}